// round 7
// baseline (speedup 1.0000x reference)
#include <cuda_runtime.h>
#include <cstdint>

// Problem constants (from reference setup_inputs)
#define MAXB   32
#define MAXN   131072
#define TILE   1024          // points per CTA (24KB smem -> 8 CTAs/SM)
#define TPB    256           // threads per CTA
#define PPT    4             // points per thread (TILE / TPB)
#define MAXTILES (MAXN / TILE)   // 128
#define NWARP  (TPB / 32)
#define NCELL  (PPT * NWARP)     // 32 == one warp

#define FLAG_AGG (1u << 30)
#define FLAG_PRE (2u << 30)
#define VALMASK  ((1u << 30) - 1u)

#define SMEM_TILE_FLOATS (TILE * 6)

// Scratch (allocation-free rule: __device__ globals; zero-init at module load;
// zero_kernel re-zeroes g_status each replay)
__device__ unsigned int g_status[MAXB * MAXTILES];
__device__ unsigned int g_batch_total[MAXB];

// Validity: bit-matches the JAX reference (verified rel_err=0.0 in R3/R4/R6).
// DO NOT change the op order / non-FMA structure.
__device__ __forceinline__ bool is_valid(float x, float y, float z,
                                         float nx, float ny, float nz,
                                         const float* __restrict__ T) {
    float px = __fadd_rn(__fadd_rn(__fadd_rn(__fmul_rn(x, T[0]), __fmul_rn(y, T[4])), __fmul_rn(z, T[8])),  T[3]);
    float py = __fadd_rn(__fadd_rn(__fadd_rn(__fmul_rn(x, T[1]), __fmul_rn(y, T[5])), __fmul_rn(z, T[9])),  T[7]);
    float pz = __fadd_rn(__fadd_rn(__fadd_rn(__fmul_rn(x, T[2]), __fmul_rn(y, T[6])), __fmul_rn(z, T[10])), T[11]);
    float sq = __fadd_rn(__fmul_rn(px, px), __fmul_rn(py, py));
    float ns = __fadd_rn(__fadd_rn(nx, ny), nz);
    return (sq < 1.0f) && (pz < 1.0f) && (ns != 0.0f);
}

__device__ __forceinline__ unsigned warp_sum(unsigned v) {
#pragma unroll
    for (int o = 16; o > 0; o >>= 1) v += __shfl_down_sync(0xFFFFFFFFu, v, o);
    return __shfl_sync(0xFFFFFFFFu, v, 0);
}

// ---------------------------------------------------------------------------
// Kernel 1: single-pass compaction, decoupled lookback.
//  - tile loaded coalesced (float4) into smem (no L1 amplification)
//  - classify from smem; ranks via per-iter ballots + warp-scanned cell grid
//  - warp 0: cell scan (shuffle) -> publish -> lookback; single barrier after
//  - valid rows stored directly from registers (valid fraction ~10%)
// Stable rank: point p = tid + i*TPB == rank order (i, tid). Verified R4/R6.
// ---------------------------------------------------------------------------
__global__ void __launch_bounds__(TPB) compact_kernel(const float* __restrict__ pc,
                                                      const float* __restrict__ tf,
                                                      float* __restrict__ out,
                                                      int N, int tiles) {
    __shared__ float sTile[SMEM_TILE_FLOATS];
    __shared__ unsigned int sScan[NCELL];   // (iter-major, warp-minor) cells
    __shared__ unsigned int sExcl;          // tile exclusive prefix

    const int b    = blockIdx.y;
    const int tile = blockIdx.x;
    const int tid  = threadIdx.x;
    const int lane = tid & 31;
    const int wid  = tid >> 5;
    const float* __restrict__ T = tf + (size_t)b * 16;

    const size_t batch_base = (size_t)b * N;
    const int tile_base = tile * TILE;

    // --- stage 1: coalesced tile load (global float4 -> smem) ---
    {
        const float4* __restrict__ gsrc =
            (const float4*)(pc + (batch_base + tile_base) * 6);
        float4* s4 = (float4*)sTile;
#pragma unroll
        for (int i = 0; i < SMEM_TILE_FLOATS / 4 / TPB; i++)
            s4[tid + i * TPB] = gsrc[tid + i * TPB];
    }
    __syncthreads();

    // --- stage 2: classify from smem ---
    float2 d[PPT][3];
    unsigned int vbits = 0;
    {
        const float2* s2 = (const float2*)sTile;
#pragma unroll
        for (int i = 0; i < PPT; i++) {
            const int p = tid + i * TPB;                   // local point idx
            d[i][0] = s2[p * 3 + 0];
            d[i][1] = s2[p * 3 + 1];
            d[i][2] = s2[p * 3 + 2];
            bool v = is_valid(d[i][0].x, d[i][0].y, d[i][1].x,
                              d[i][1].y, d[i][2].x, d[i][2].y, T);
            vbits |= (v ? 1u : 0u) << i;
        }
    }

    // --- ballots -> (iter, warp) cell counts ---
    unsigned int ball[PPT];
#pragma unroll
    for (int i = 0; i < PPT; i++) {
        ball[i] = __ballot_sync(0xFFFFFFFFu, (vbits >> i) & 1u);
        if (lane == 0) sScan[i * NWARP + wid] = __popc(ball[i]);
    }
    __syncthreads();

    // --- warp 0: shuffle-scan 32 cells, publish aggregate, lookback ---
    if (wid == 0) {
        unsigned int v = sScan[lane];
        unsigned int x = v;
#pragma unroll
        for (int o = 1; o < 32; o <<= 1) {
            unsigned int y = __shfl_up_sync(0xFFFFFFFFu, x, o);
            if (lane >= o) x += y;
        }
        sScan[lane] = x - v;                               // exclusive scan
        const unsigned int cnt = __shfl_sync(0xFFFFFFFFu, x, 31);

        unsigned int* st = &g_status[b * tiles + tile];
        if (lane == 0)
            *(volatile unsigned int*)st = (tile == 0 ? FLAG_PRE : FLAG_AGG) | cnt;

        unsigned int running = 0;
        if (tile > 0) {
            int j = tile - 1;
            for (;;) {
                const int idx = j - lane;
                unsigned int s = 0;
                if (idx >= 0) {
                    do { s = *(volatile unsigned int*)&g_status[b * tiles + idx]; }
                    while ((s >> 30) == 0u);
                }
                const unsigned int pmask = __ballot_sync(0xFFFFFFFFu,
                                                         idx >= 0 && (s >> 30) == 2u);
                if (pmask) {
                    const int firstPre = __ffs(pmask) - 1;
                    unsigned int contrib = (idx >= 0 && lane <= firstPre) ? (s & VALMASK) : 0u;
                    running += warp_sum(contrib);
                    break;
                } else {
                    unsigned int contrib = (idx >= 0) ? (s & VALMASK) : 0u;
                    running += warp_sum(contrib);
                    j -= 32;
                }
            }
        }
        if (lane == 0) {
            sExcl = running;
            if (tile > 0)
                *(volatile unsigned int*)st = FLAG_PRE | (running + cnt);
            if (tile == tiles - 1)
                g_batch_total[b] = running + cnt;
        }
    }
    __syncthreads();

    // --- stage 3: direct stores of valid rows from registers ---
    const unsigned int exclTile = sExcl;
    const unsigned int lmask = (1u << lane) - 1u;
#pragma unroll
    for (int i = 0; i < PPT; i++) {
        if ((vbits >> i) & 1u) {
            const unsigned int rank = sScan[i * NWARP + wid] + __popc(ball[i] & lmask);
            float2* o = (float2*)(out + (batch_base + exclTile + rank) * 6);
            __stcs(o + 0, d[i][0]);
            __stcs(o + 1, d[i][1]);
            __stcs(o + 2, d[i][2]);
        }
    }
}

// ---------------------------------------------------------------------------
// Kernel 2: zero-fill tail rows [K_b, N); resets g_status for the next replay.
// STG.128 body after aligning the head to a float4 boundary.
// ---------------------------------------------------------------------------
__global__ void __launch_bounds__(TPB) zero_kernel(float* __restrict__ out,
                                                   int N, int tiles) {
    const int b    = blockIdx.y;
    const int tile = blockIdx.x;
    const int tid  = threadIdx.x;
    if (tid == 0) g_status[b * tiles + tile] = 0u;         // reset for next replay
    const long long Kf = (long long)g_batch_total[b] * 6;  // first float to zero
    const long long f0 = (long long)tile * TILE * 6;
    const long long f1 = f0 + (long long)TILE * 6;         // multiple of 4
    long long lo = Kf > f0 ? Kf : f0;
    if (lo >= f1) return;
    float* base = out + (size_t)b * N * 6;                 // 16B-aligned
    const long long lo4 = (lo + 3) & ~3LL;                 // align head
    if (tid < (int)(lo4 - lo)) base[lo + tid] = 0.0f;
    float4* b4 = (float4*)base;
    const float4 z4 = make_float4(0.0f, 0.0f, 0.0f, 0.0f);
    for (long long i = (lo4 >> 2) + tid; i < (f1 >> 2); i += TPB)
        __stcs(b4 + i, z4);
}

// ---------------------------------------------------------------------------
extern "C" void kernel_launch(void* const* d_in, const int* in_sizes, int n_in,
                              void* d_out, int out_size) {
    const float* pc = (const float*)d_in[0];   // pointclouds (B, N, 6)
    const float* tf = (const float*)d_in[1];   // task_transform (B, 4, 4)

    const int B = in_sizes[1] / 16;
    const int N = (int)((long long)in_sizes[0] / (6LL * B));
    const int tiles = N / TILE;

    dim3 grid(tiles, B);
    compact_kernel<<<grid, TPB>>>(pc, tf, (float*)d_out, N, tiles);
    zero_kernel<<<grid, TPB>>>((float*)d_out, N, tiles);
}

// round 8
// speedup vs baseline: 1.7803x; 1.7803x over previous
#include <cuda_runtime.h>
#include <cstdint>

// Problem constants (from reference setup_inputs)
#define MAXB   32
#define MAXN   131072
#define TILE   2048          // points per CTA
#define TPB    256           // threads per CTA
#define PPT    8             // points per thread (TILE / TPB)
#define MAXTILES (MAXN / TILE)   // 64
#define NWARP  (TPB / 32)
#define NCELL  (PPT * NWARP)     // 64 cells -> pair-scan in one warp

#define SMEM_TILE_FLOATS (TILE * 6)
#define SMEM_BYTES (SMEM_TILE_FLOATS * 4 + (NCELL + 4) * 4)

// Scratch (allocation-free rule: __device__ globals). ~96 MiB staging buffer:
// tile t of batch b stages its compacted valid rows at rows [t*TILE, t*TILE+cnt).
__device__ float        g_scratch[(size_t)MAXB * MAXN * 6];
__device__ unsigned int g_cnt[MAXB * MAXTILES];

// Validity: bit-matches the JAX reference (verified rel_err=0.0 R3/R4/R6/R7).
// DO NOT change the op order / non-FMA structure.
__device__ __forceinline__ bool is_valid(float x, float y, float z,
                                         float nx, float ny, float nz,
                                         const float* __restrict__ T) {
    float px = __fadd_rn(__fadd_rn(__fadd_rn(__fmul_rn(x, T[0]), __fmul_rn(y, T[4])), __fmul_rn(z, T[8])),  T[3]);
    float py = __fadd_rn(__fadd_rn(__fadd_rn(__fmul_rn(x, T[1]), __fmul_rn(y, T[5])), __fmul_rn(z, T[9])),  T[7]);
    float pz = __fadd_rn(__fadd_rn(__fadd_rn(__fmul_rn(x, T[2]), __fmul_rn(y, T[6])), __fmul_rn(z, T[10])), T[11]);
    float sq = __fadd_rn(__fmul_rn(px, px), __fmul_rn(py, py));
    float ns = __fadd_rn(__fadd_rn(nx, ny), nz);
    return (sq < 1.0f) && (pz < 1.0f) && (ns != 0.0f);
}

// ---------------------------------------------------------------------------
// Kernel 1: stage. Per tile: classify, rank, write count + compacted valid
// rows into g_scratch at the tile's own base. NO inter-CTA communication.
// Stable rank: point p = i*TPB + tid == order (i, tid); cells k = i*NWARP+wid
// are contiguous 32-point blocks in increasing p (verified R4/R6).
// ---------------------------------------------------------------------------
__global__ void __launch_bounds__(TPB) stage_kernel(const float* __restrict__ pc,
                                                    const float* __restrict__ tf,
                                                    int N, int tiles) {
    extern __shared__ float sTile[];                       // TILE*6 floats
    unsigned int* sScan  = (unsigned int*)(sTile + SMEM_TILE_FLOATS);  // NCELL
    unsigned int* sTotal = sScan + NCELL;

    const int b    = blockIdx.y;
    const int tile = blockIdx.x;
    const int tid  = threadIdx.x;
    const int lane = tid & 31;
    const int wid  = tid >> 5;
    const float* __restrict__ T = tf + (size_t)b * 16;

    const size_t batch_base = (size_t)b * N;
    const int tile_base = tile * TILE;

    // --- coalesced tile load; .cs (read-once) protects scratch L2 residency ---
    {
        const float4* __restrict__ gsrc =
            (const float4*)(pc + (batch_base + tile_base) * 6);
        float4* s4 = (float4*)sTile;
#pragma unroll
        for (int i = 0; i < SMEM_TILE_FLOATS / 4 / TPB; i++)
            s4[tid + i * TPB] = __ldcs(gsrc + tid + i * TPB);
    }
    __syncthreads();

    // --- classify from smem ---
    float2 d[PPT][3];
    unsigned int vbits = 0;
    {
        const float2* s2 = (const float2*)sTile;
#pragma unroll
        for (int i = 0; i < PPT; i++) {
            const int p = tid + i * TPB;
            d[i][0] = s2[p * 3 + 0];
            d[i][1] = s2[p * 3 + 1];
            d[i][2] = s2[p * 3 + 2];
            bool v = is_valid(d[i][0].x, d[i][0].y, d[i][1].x,
                              d[i][1].y, d[i][2].x, d[i][2].y, T);
            vbits |= (v ? 1u : 0u) << i;
        }
    }

    // --- ballots -> 64 cell counts ---
    unsigned int ball[PPT];
#pragma unroll
    for (int i = 0; i < PPT; i++) {
        ball[i] = __ballot_sync(0xFFFFFFFFu, (vbits >> i) & 1u);
        if (lane == 0) sScan[i * NWARP + wid] = __popc(ball[i]);
    }
    __syncthreads();

    // --- warp 0: exclusive scan of 64 cells (2 per lane), publish count ---
    if (wid == 0) {
        unsigned int a  = sScan[2 * lane];
        unsigned int bb = sScan[2 * lane + 1];
        unsigned int s  = a + bb;
        unsigned int x  = s;
#pragma unroll
        for (int o = 1; o < 32; o <<= 1) {
            unsigned int y = __shfl_up_sync(0xFFFFFFFFu, x, o);
            if (lane >= o) x += y;
        }
        const unsigned int excl = x - s;
        sScan[2 * lane]     = excl;
        sScan[2 * lane + 1] = excl + a;
        if (lane == 31) { *sTotal = x; g_cnt[b * tiles + tile] = x; }
    }
    __syncthreads();
    const unsigned int cnt   = *sTotal;
    const unsigned int lmask = (1u << lane) - 1u;

    // --- compact valid rows into smem (reuse tile buffer; data is in regs) ---
    {
        float2* s2 = (float2*)sTile;
#pragma unroll
        for (int i = 0; i < PPT; i++) {
            if ((vbits >> i) & 1u) {
                const unsigned int rank = sScan[i * NWARP + wid] + __popc(ball[i] & lmask);
                s2[rank * 3 + 0] = d[i][0];
                s2[rank * 3 + 1] = d[i][1];
                s2[rank * 3 + 2] = d[i][2];
            }
        }
    }
    __syncthreads();

    // --- coalesced store of compacted block to scratch (default policy: keep in L2) ---
    float2* __restrict__ gdst = (float2*)(g_scratch + (batch_base + tile_base) * 6);
    const float2* s2 = (const float2*)sTile;
    const unsigned int nF2 = cnt * 3;
    for (unsigned int i = tid; i < nF2; i += TPB)
        gdst[i] = s2[i];
}

// ---------------------------------------------------------------------------
// Kernel 2: gather + zero. Warp 0 redundantly scans the batch's 64 counts
// (L2-hot, 256B) -> exact prefix & K_b, no spinning. Then:
//   copy scratch[tile_base .. +cnt) -> out[prefix .. +cnt)   (L2-hit reads)
//   zero out rows in this tile's output slice that fall in [K_b, N)
// ---------------------------------------------------------------------------
__global__ void __launch_bounds__(TPB) gather_zero_kernel(float* __restrict__ out,
                                                          int N, int tiles) {
    __shared__ unsigned int sMeta[3];   // [0]=prefix, [1]=K_b, [2]=cnt

    const int b    = blockIdx.y;
    const int tile = blockIdx.x;
    const int tid  = threadIdx.x;
    const int lane = tid & 31;
    const int wid  = tid >> 5;
    const size_t batch_base = (size_t)b * N;

    if (wid == 0) {
        const unsigned int c0 = g_cnt[b * tiles + 2 * lane];
        const unsigned int c1 = g_cnt[b * tiles + 2 * lane + 1];
        unsigned int s = c0 + c1;
        unsigned int x = s;
#pragma unroll
        for (int o = 1; o < 32; o <<= 1) {
            unsigned int y = __shfl_up_sync(0xFFFFFFFFu, x, o);
            if (lane >= o) x += y;
        }
        const unsigned int excl  = x - s;
        const unsigned int total = __shfl_sync(0xFFFFFFFFu, x, 31);
        const unsigned int pe  = __shfl_sync(0xFFFFFFFFu, excl, tile >> 1);
        const unsigned int po  = __shfl_sync(0xFFFFFFFFu, excl + c0, tile >> 1);
        const unsigned int mcE = __shfl_sync(0xFFFFFFFFu, c0, tile >> 1);
        const unsigned int mcO = __shfl_sync(0xFFFFFFFFu, c1, tile >> 1);
        if (lane == 0) {
            sMeta[0] = (tile & 1) ? po  : pe;
            sMeta[1] = total;
            sMeta[2] = (tile & 1) ? mcO : mcE;
        }
    }
    __syncthreads();
    const unsigned int prefix = sMeta[0];
    const unsigned int Kb     = sMeta[1];
    const unsigned int cnt    = sMeta[2];

    // --- copy valid block: scratch (L2-resident) -> final position ---
    {
        const float2* __restrict__ src =
            (const float2*)(g_scratch + (batch_base + (size_t)tile * TILE) * 6);
        float2* __restrict__ dst = (float2*)(out + (batch_base + prefix) * 6);
        const unsigned int nF2 = cnt * 3;
        for (unsigned int i = tid; i < nF2; i += TPB)
            __stcs(dst + i, src[i]);
    }

    // --- zero this tile's share of the tail [K_b, N) ---
    const long long Kf = (long long)Kb * 6;
    const long long f0 = (long long)tile * TILE * 6;
    const long long f1 = f0 + (long long)TILE * 6;         // multiple of 4
    long long lo = Kf > f0 ? Kf : f0;
    if (lo >= f1) return;
    float* base = out + batch_base * 6;                    // 16B-aligned
    const long long lo4 = (lo + 3) & ~3LL;                 // align head
    if (tid < (int)(lo4 - lo)) base[lo + tid] = 0.0f;
    float4* b4 = (float4*)base;
    const float4 z4 = make_float4(0.0f, 0.0f, 0.0f, 0.0f);
    for (long long i = (lo4 >> 2) + tid; i < (f1 >> 2); i += TPB)
        __stcs(b4 + i, z4);
}

// ---------------------------------------------------------------------------
extern "C" void kernel_launch(void* const* d_in, const int* in_sizes, int n_in,
                              void* d_out, int out_size) {
    const float* pc = (const float*)d_in[0];   // pointclouds (B, N, 6)
    const float* tf = (const float*)d_in[1];   // task_transform (B, 4, 4)

    const int B = in_sizes[1] / 16;
    const int N = (int)((long long)in_sizes[0] / (6LL * B));
    const int tiles = N / TILE;

    cudaFuncSetAttribute(stage_kernel,
                         cudaFuncAttributeMaxDynamicSharedMemorySize, SMEM_BYTES);

    dim3 grid(tiles, B);
    stage_kernel<<<grid, TPB, SMEM_BYTES>>>(pc, tf, N, tiles);
    gather_zero_kernel<<<grid, TPB>>>((float*)d_out, N, tiles);
}

// round 9
// speedup vs baseline: 1.7957x; 1.0086x over previous
#include <cuda_runtime.h>
#include <cstdint>

// Problem constants (from reference setup_inputs)
#define MAXB   32
#define MAXN   131072
#define TILE   2048          // points per CTA
#define TPB    256           // threads per CTA
#define PPT    8             // points per thread (TILE / TPB)
#define MAXTILES (MAXN / TILE)   // 64
#define NWARP  (TPB / 32)
#define NCELL  (PPT * NWARP)     // 64 cells -> pair-scan in one warp

#define SMEM_TILE_FLOATS (TILE * 6)
#define SMEM_BYTES (SMEM_TILE_FLOATS * 4 + (NCELL + 4) * 4)

// Scratch (allocation-free rule: __device__ globals). ~96 MiB staging buffer:
// tile t of batch b stages its compacted valid rows at rows [t*TILE, t*TILE+cnt).
__device__ float        g_scratch[(size_t)MAXB * MAXN * 6];
__device__ unsigned int g_cnt[MAXB * MAXTILES];

// Validity: bit-matches the JAX reference (verified rel_err=0.0 R3/R4/R6-R8).
// DO NOT change the op order / non-FMA structure.
__device__ __forceinline__ bool is_valid(float x, float y, float z,
                                         float nx, float ny, float nz,
                                         const float* __restrict__ T) {
    float px = __fadd_rn(__fadd_rn(__fadd_rn(__fmul_rn(x, T[0]), __fmul_rn(y, T[4])), __fmul_rn(z, T[8])),  T[3]);
    float py = __fadd_rn(__fadd_rn(__fadd_rn(__fmul_rn(x, T[1]), __fmul_rn(y, T[5])), __fmul_rn(z, T[9])),  T[7]);
    float pz = __fadd_rn(__fadd_rn(__fadd_rn(__fmul_rn(x, T[2]), __fmul_rn(y, T[6])), __fmul_rn(z, T[10])), T[11]);
    float sq = __fadd_rn(__fmul_rn(px, px), __fmul_rn(py, py));
    float ns = __fadd_rn(__fadd_rn(nx, ny), nz);
    return (sq < 1.0f) && (pz < 1.0f) && (ns != 0.0f);
}

// ---------------------------------------------------------------------------
// Kernel 1: stage. Per tile: classify, rank, write count + compacted valid
// rows into g_scratch at the tile's own base. NO inter-CTA communication.
// Valid rows go straight from registers to scratch (only ~10% of points, so
// scatter cost is small; saves a barrier + 20MB of smem round-trip traffic).
// Stable rank: point p = i*TPB + tid == order (i, tid); cells k = i*NWARP+wid
// are contiguous 32-point blocks in increasing p (verified R4/R6/R8).
// ---------------------------------------------------------------------------
__global__ void __launch_bounds__(TPB) stage_kernel(const float* __restrict__ pc,
                                                    const float* __restrict__ tf,
                                                    int N, int tiles) {
    extern __shared__ float sTile[];                       // TILE*6 floats
    unsigned int* sScan = (unsigned int*)(sTile + SMEM_TILE_FLOATS);  // NCELL

    const int b    = blockIdx.y;
    const int tile = blockIdx.x;
    const int tid  = threadIdx.x;
    const int lane = tid & 31;
    const int wid  = tid >> 5;
    const float* __restrict__ T = tf + (size_t)b * 16;

    const size_t batch_base = (size_t)b * N;
    const int tile_base = tile * TILE;

    // --- coalesced tile load; .cs (read-once) protects scratch L2 residency ---
    {
        const float4* __restrict__ gsrc =
            (const float4*)(pc + (batch_base + tile_base) * 6);
        float4* s4 = (float4*)sTile;
#pragma unroll
        for (int i = 0; i < SMEM_TILE_FLOATS / 4 / TPB; i++)
            s4[tid + i * TPB] = __ldcs(gsrc + tid + i * TPB);
    }
    __syncthreads();

    // --- classify from smem ---
    float2 d[PPT][3];
    unsigned int vbits = 0;
    {
        const float2* s2 = (const float2*)sTile;
#pragma unroll
        for (int i = 0; i < PPT; i++) {
            const int p = tid + i * TPB;
            d[i][0] = s2[p * 3 + 0];
            d[i][1] = s2[p * 3 + 1];
            d[i][2] = s2[p * 3 + 2];
            bool v = is_valid(d[i][0].x, d[i][0].y, d[i][1].x,
                              d[i][1].y, d[i][2].x, d[i][2].y, T);
            vbits |= (v ? 1u : 0u) << i;
        }
    }

    // --- ballots -> 64 cell counts ---
    unsigned int ball[PPT];
#pragma unroll
    for (int i = 0; i < PPT; i++) {
        ball[i] = __ballot_sync(0xFFFFFFFFu, (vbits >> i) & 1u);
        if (lane == 0) sScan[i * NWARP + wid] = __popc(ball[i]);
    }
    __syncthreads();

    // --- warp 0: exclusive scan of 64 cells (2 per lane), publish count ---
    if (wid == 0) {
        unsigned int a  = sScan[2 * lane];
        unsigned int bb = sScan[2 * lane + 1];
        unsigned int s  = a + bb;
        unsigned int x  = s;
#pragma unroll
        for (int o = 1; o < 32; o <<= 1) {
            unsigned int y = __shfl_up_sync(0xFFFFFFFFu, x, o);
            if (lane >= o) x += y;
        }
        const unsigned int excl = x - s;
        sScan[2 * lane]     = excl;
        sScan[2 * lane + 1] = excl + a;
        if (lane == 31) g_cnt[b * tiles + tile] = x;
    }
    __syncthreads();

    // --- direct register scatter of valid rows to scratch ---
    const unsigned int lmask = (1u << lane) - 1u;
    float2* __restrict__ gdst = (float2*)(g_scratch + (batch_base + tile_base) * 6);
#pragma unroll
    for (int i = 0; i < PPT; i++) {
        if ((vbits >> i) & 1u) {
            const unsigned int rank = sScan[i * NWARP + wid] + __popc(ball[i] & lmask);
            gdst[rank * 3 + 0] = d[i][0];
            gdst[rank * 3 + 1] = d[i][1];
            gdst[rank * 3 + 2] = d[i][2];
        }
    }
}

// ---------------------------------------------------------------------------
// Kernel 2: gather + zero. Warp 0 redundantly scans the batch's 64 counts
// (L2-hot, 256B) -> exact prefix & K_b, no spinning. Then:
//   copy scratch[tile_base .. +cnt) -> out[prefix .. +cnt)   (L2-hit reads)
//   zero out rows in this tile's output slice that fall in [K_b, N)
// Copy uses float4 when the destination is 16B-aligned (prefix even).
// ---------------------------------------------------------------------------
__global__ void __launch_bounds__(TPB) gather_zero_kernel(float* __restrict__ out,
                                                          int N, int tiles) {
    __shared__ unsigned int sMeta[3];   // [0]=prefix, [1]=K_b, [2]=cnt

    const int b    = blockIdx.y;
    const int tile = blockIdx.x;
    const int tid  = threadIdx.x;
    const int lane = tid & 31;
    const int wid  = tid >> 5;
    const size_t batch_base = (size_t)b * N;

    if (wid == 0) {
        const unsigned int c0 = g_cnt[b * tiles + 2 * lane];
        const unsigned int c1 = g_cnt[b * tiles + 2 * lane + 1];
        unsigned int s = c0 + c1;
        unsigned int x = s;
#pragma unroll
        for (int o = 1; o < 32; o <<= 1) {
            unsigned int y = __shfl_up_sync(0xFFFFFFFFu, x, o);
            if (lane >= o) x += y;
        }
        const unsigned int excl  = x - s;
        const unsigned int total = __shfl_sync(0xFFFFFFFFu, x, 31);
        const unsigned int pe  = __shfl_sync(0xFFFFFFFFu, excl, tile >> 1);
        const unsigned int po  = __shfl_sync(0xFFFFFFFFu, excl + c0, tile >> 1);
        const unsigned int mcE = __shfl_sync(0xFFFFFFFFu, c0, tile >> 1);
        const unsigned int mcO = __shfl_sync(0xFFFFFFFFu, c1, tile >> 1);
        if (lane == 0) {
            sMeta[0] = (tile & 1) ? po  : pe;
            sMeta[1] = total;
            sMeta[2] = (tile & 1) ? mcO : mcE;
        }
    }
    __syncthreads();
    const unsigned int prefix = sMeta[0];
    const unsigned int Kb     = sMeta[1];
    const unsigned int cnt    = sMeta[2];

    // --- copy valid block: scratch (L2-resident) -> final position ---
    {
        const float* __restrict__ srcf =
            g_scratch + (batch_base + (size_t)tile * TILE) * 6;
        float* __restrict__ dstf = out + (batch_base + prefix) * 6;
        const unsigned int nF = cnt * 6;                   // floats to copy
        if ((prefix & 1u) == 0u) {
            // dst 16B-aligned (prefix*24 % 16 == 0): float4 body + float2 tail
            const float4* __restrict__ s4 = (const float4*)srcf;
            float4* __restrict__ d4 = (float4*)dstf;
            const unsigned int nF4 = nF >> 2;
            for (unsigned int i = tid; i < nF4; i += TPB)
                __stcs(d4 + i, s4[i]);
            if (tid == 0 && (nF & 3u))                     // cnt odd: 2 floats left
                __stcs((float2*)(dstf + (nF4 << 2)),
                       *(const float2*)(srcf + (nF4 << 2)));
        } else {
            const float2* __restrict__ s2 = (const float2*)srcf;
            float2* __restrict__ d2 = (float2*)dstf;
            const unsigned int nF2 = nF >> 1;
            for (unsigned int i = tid; i < nF2; i += TPB)
                __stcs(d2 + i, s2[i]);
        }
    }

    // --- zero this tile's share of the tail [K_b, N) ---
    const long long Kf = (long long)Kb * 6;
    const long long f0 = (long long)tile * TILE * 6;
    const long long f1 = f0 + (long long)TILE * 6;         // multiple of 4
    long long lo = Kf > f0 ? Kf : f0;
    if (lo >= f1) return;
    float* base = out + batch_base * 6;                    // 16B-aligned
    const long long lo4 = (lo + 3) & ~3LL;                 // align head
    if (tid < (int)(lo4 - lo)) base[lo + tid] = 0.0f;
    float4* b4 = (float4*)base;
    const float4 z4 = make_float4(0.0f, 0.0f, 0.0f, 0.0f);
    for (long long i = (lo4 >> 2) + tid; i < (f1 >> 2); i += TPB)
        __stcs(b4 + i, z4);
}

// ---------------------------------------------------------------------------
extern "C" void kernel_launch(void* const* d_in, const int* in_sizes, int n_in,
                              void* d_out, int out_size) {
    const float* pc = (const float*)d_in[0];   // pointclouds (B, N, 6)
    const float* tf = (const float*)d_in[1];   // task_transform (B, 4, 4)

    const int B = in_sizes[1] / 16;
    const int N = (int)((long long)in_sizes[0] / (6LL * B));
    const int tiles = N / TILE;

    cudaFuncSetAttribute(stage_kernel,
                         cudaFuncAttributeMaxDynamicSharedMemorySize, SMEM_BYTES);

    dim3 grid(tiles, B);
    stage_kernel<<<grid, TPB, SMEM_BYTES>>>(pc, tf, N, tiles);
    gather_zero_kernel<<<grid, TPB>>>((float*)d_out, N, tiles);
}